// round 3
// baseline (speedup 1.0000x reference)
#include <cuda_runtime.h>

#define NN 20000
#define NE 400000
#define FD 64
#define CT 64
#define HD 128
#define TS 6
#define KD 67      // F + 3 label channels

// ---------------- scratch (static device globals; no allocation) -------------
__device__ int   g_flagA[NN];
__device__ int   g_flagB[NN];
__device__ int   g_isc[NN];
__device__ int   g_cnt[NN];      // in-degree (all edges) per dst
__device__ int   g_off[NN];      // CSR row offsets
__device__ int   g_cur[NN];      // fill cursors
__device__ int   g_csrc[NE];     // CSR src indices (grouped by dst)
__device__ float g_dinv[NN];
__device__ float g_selfn[NN];
__device__ float g_h1[NN * HD];
__device__ float g_sv[NN];
__device__ unsigned long long g_packed;
__device__ float g_seq[TS * HD];

// ---------------- kernels ----------------------------------------------------

__global__ void k_init() {
    int i = blockIdx.x * blockDim.x + threadIdx.x;
    if (i < NN) { g_flagA[i] = 0; g_flagB[i] = 0; g_isc[i] = 0; g_cnt[i] = 0; }
    if (i == 0) g_packed = 0ull;
}

__global__ void k_targets(const int* __restrict__ tgt) {
    int j = threadIdx.x;
    if (j < CT) {
        int n = tgt[j];
        g_flagA[n] = 1; g_flagB[n] = 1; g_isc[n] = 1;
    }
}

// hop 1 (read A -> write B) fused with CSR degree count
__global__ void k_prop1cnt(const int* __restrict__ ei) {
    int e = blockIdx.x * blockDim.x + threadIdx.x;
    if (e >= NE) return;
    int s = ei[e], d = ei[NE + e];
    atomicAdd(&g_cnt[d], 1);
    if (g_flagA[s]) g_flagB[d] = 1;
    if (g_flagA[d]) g_flagB[s] = 1;
}

// single-block exclusive scan of g_cnt -> g_off, g_cur
__global__ void __launch_bounds__(1024) k_scan() {
    __shared__ int sp[1024];
    const int CH = 20;                 // 1024*20 >= NN
    int t = threadIdx.x;
    int base = t * CH;
    int local[CH];
    int s = 0;
    #pragma unroll
    for (int j = 0; j < CH; j++) {
        int v = (base + j < NN) ? g_cnt[base + j] : 0;
        local[j] = v; s += v;
    }
    sp[t] = s;
    __syncthreads();
    for (int o = 1; o < 1024; o <<= 1) {
        int v = (t >= o) ? sp[t - o] : 0;
        __syncthreads();
        sp[t] += v;
        __syncthreads();
    }
    int run = sp[t] - s;               // exclusive prefix
    #pragma unroll
    for (int j = 0; j < CH; j++) {
        int i = base + j;
        if (i < NN) { g_off[i] = run; g_cur[i] = run; }
        run += local[j];
    }
}

// hop 2 (read B -> write A; A already holds targets) fused with CSR fill
__global__ void k_prop2fill(const int* __restrict__ ei) {
    int e = blockIdx.x * blockDim.x + threadIdx.x;
    if (e >= NE) return;
    int s = ei[e], d = ei[NE + e];
    if (g_flagB[s]) g_flagA[d] = 1;
    if (g_flagB[d]) g_flagA[s] = 1;
    int p = atomicAdd(&g_cur[d], 1);
    g_csrc[p] = s;
}

// per-node: deg over in-subgraph in-edges (via CSR) -> dinv, selfn
__global__ void k_dinv() {
    int gid  = blockIdx.x * blockDim.x + threadIdx.x;
    int i    = gid >> 5;
    int lane = gid & 31;
    if (i >= NN) return;
    if (!g_flagA[i]) {
        if (lane == 0) { g_dinv[i] = 0.f; g_selfn[i] = 0.f; }
        return;
    }
    int o = g_off[i], c = g_cnt[i];
    int deg = 0;
    for (int e = lane; e < c; e += 32)
        deg += g_flagA[g_csrc[o + e]] ? 1 : 0;
    #pragma unroll
    for (int off = 16; off > 0; off >>= 1)
        deg += __shfl_down_sync(0xffffffffu, deg, off);
    if (lane == 0) {
        float di = rsqrtf((float)deg + 1.0f);   // + self loop
        g_dinv[i]  = di;
        g_selfn[i] = di * di;
    }
}

// fused: CSR gather of 67-dim normalized aggregation + W1 GEMM + relu
//        + sv = h1 @ W2[:,127].  Warp-per-node gather (lane-parallel edge
//        metadata + shfl broadcast), block GEMM.
__global__ void __launch_bounds__(128) k_layer1(const float* __restrict__ x,
                                                const float* __restrict__ W1,
                                                const float* __restrict__ b1,
                                                const float* __restrict__ W2) {
    __shared__ float szrow[4][KD + 1];   // 4 nodes' z rows
    __shared__ int   sact[4];
    __shared__ float sred[4][4];         // [warp][node] partial sv sums
    int t    = threadIdx.x;
    int wid  = t >> 5;
    int lane = t & 31;

    float rw[KD];
    #pragma unroll
    for (int k = 0; k < KD; k++) rw[k] = W1[k * HD + t];   // W1 column t
    float w2c = W2[t * HD + (HD - 1)];
    float bb  = b1[t];

    for (int i0 = blockIdx.x * 4; i0 < NN; i0 += gridDim.x * 4) {
        int i = i0 + wid;
        int active = 0;
        if (i < NN) {
            float di = g_dinv[i];
            if (di != 0.f) {
                active = 1;
                int o = g_off[i], c = g_cnt[i];
                float a0 = 0.f, a1 = 0.f, wc = 0.f, wo = 0.f;
                for (int base = 0; base < c; base += 32) {
                    int rem = c - base;
                    // lane-parallel metadata fetch (breaks dependent chain)
                    int   sl = 0; float wl = 0.f; int icl = 0;
                    if (lane < rem) {
                        sl  = g_csrc[o + base + lane];
                        wl  = g_dinv[sl] * di;
                        icl = g_isc[sl];
                    }
                    wc += icl ? wl : 0.f;
                    wo += icl ? 0.f : wl;
                    int nn = rem < 32 ? rem : 32;
                    for (int e = 0; e < nn; e++) {
                        float w = __shfl_sync(0xffffffffu, wl, e);
                        if (w != 0.f) {
                            int s = __shfl_sync(0xffffffffu, sl, e);
                            a0 += x[s * FD + lane] * w;
                            a1 += x[s * FD + 32 + lane] * w;
                        }
                    }
                }
                // self-loop contribution
                float sn = g_selfn[i];
                a0 += x[i * FD + lane] * sn;
                a1 += x[i * FD + 32 + lane] * sn;
                szrow[wid][lane]      = a0;
                szrow[wid][lane + 32] = a1;
                // reduce label-channel sums across the warp
                #pragma unroll
                for (int off = 16; off > 0; off >>= 1) {
                    wc += __shfl_down_sync(0xffffffffu, wc, off);
                    wo += __shfl_down_sync(0xffffffffu, wo, off);
                }
                if (lane == 0) {
                    int ic = g_isc[i];
                    szrow[wid][64] = wc + (ic ? sn : 0.f);
                    szrow[wid][65] = wo + (ic ? 0.f : sn);
                    szrow[wid][66] = 0.f;
                }
            }
        }
        if (lane == 0) sact[wid] = active;
        __syncthreads();

        // ---- GEMM phase: thread t = output channel t, all 4 nodes ----
        float pv[4];
        #pragma unroll
        for (int r = 0; r < 4; r++) {
            pv[r] = 0.f;
            if (!sact[r]) continue;
            float acc = bb;
            #pragma unroll
            for (int k = 0; k < KD; k++) acc += szrow[r][k] * rw[k];
            float hv = fmaxf(acc, 0.f);
            g_h1[(i0 + r) * HD + t] = hv;
            pv[r] = hv * w2c;
        }
        #pragma unroll
        for (int r = 0; r < 4; r++) {
            float p = pv[r];
            #pragma unroll
            for (int off = 16; off > 0; off >>= 1)
                p += __shfl_down_sync(0xffffffffu, p, off);
            if (lane == 0) sred[wid][r] = p;
        }
        __syncthreads();
        if (t < 4 && sact[t])
            g_sv[i0 + t] = sred[0][t] + sred[1][t] + sred[2][t] + sred[3][t];
        __syncthreads();
    }
}

// fused: scalar layer-2 gather + argmax (packed value|~index atomicMax)
__global__ void k_zs_argmax(const float* __restrict__ b2) {
    int gid  = blockIdx.x * blockDim.x + threadIdx.x;
    int i    = gid >> 5;
    int lane = gid & 31;
    if (i >= NN) return;
    if (!g_flagA[i]) return;
    float di = g_dinv[i];
    int o = g_off[i], c = g_cnt[i];
    float acc = 0.f;
    for (int e = lane; e < c; e += 32) {
        int s = g_csrc[o + e];
        acc += g_sv[s] * g_dinv[s];
    }
    #pragma unroll
    for (int off = 16; off > 0; off >>= 1)
        acc += __shfl_down_sync(0xffffffffu, acc, off);
    if (lane == 0) {
        float v = acc * di + g_sv[i] * g_selfn[i] + b2[HD - 1];
        v = fmaxf(v, 0.f);   // relu output >= 0: bits monotone as unsigned
        unsigned long long key =
            ((unsigned long long)__float_as_uint(v) << 32) |
            (unsigned long long)(0xFFFFFFFFu - (unsigned)i);
        atomicMax(&g_packed, key);
    }
}

// single block: gather top node's 128-dim layer-2 row via its CSR row,
// GEMV with W2, relu, write seq[t]
__global__ void __launch_bounds__(128) k_top(const float* __restrict__ W2,
                                             const float* __restrict__ b2,
                                             int t) {
    __shared__ float zf[HD];
    __shared__ int stop_s;
    int tid = threadIdx.x;
    if (tid == 0)
        stop_s = (int)(0xFFFFFFFFu - (unsigned)(g_packed & 0xFFFFFFFFull));
    __syncthreads();
    int top = stop_s;
    float di = g_dinv[top];
    int o = g_off[top], c = g_cnt[top];
    float acc = g_h1[top * HD + tid] * g_selfn[top];
    for (int e = 0; e < c; e++) {
        int s   = g_csrc[o + e];
        float w = g_dinv[s] * di;
        if (w != 0.f) acc += g_h1[s * HD + tid] * w;
    }
    zf[tid] = acc;
    __syncthreads();
    float a = b2[tid];
    #pragma unroll 8
    for (int k = 0; k < HD; k++) a += zf[k] * W2[k * HD + tid];
    g_seq[t * HD + tid] = fmaxf(a, 0.f);
}

// GRU over 6 steps + classifier head; single block of 384 threads
__global__ void k_gru(const float* __restrict__ Wih, const float* __restrict__ Whh,
                      const float* __restrict__ bih, const float* __restrict__ bhh,
                      const float* __restrict__ Wc1, const float* __restrict__ bc1,
                      const float* __restrict__ Wc2, const float* __restrict__ bc2,
                      float* __restrict__ out) {
    __shared__ float h[HD], xt[HD], gi[3 * HD], gh[3 * HD], hid[HD / 2];
    int j = threadIdx.x;
    if (j < HD) h[j] = 0.f;
    __syncthreads();
    for (int t = 0; t < TS; t++) {
        if (j < HD) xt[j] = g_seq[t * HD + j];
        __syncthreads();
        float a = bih[j], b = bhh[j];
        #pragma unroll 8
        for (int k = 0; k < HD; k++) {
            a += Wih[j * HD + k] * xt[k];
            b += Whh[j * HD + k] * h[k];
        }
        gi[j] = a; gh[j] = b;
        __syncthreads();
        if (j < HD) {
            float r  = 1.f / (1.f + expf(-(gi[j] + gh[j])));
            float z  = 1.f / (1.f + expf(-(gi[HD + j] + gh[HD + j])));
            float n  = tanhf(gi[2 * HD + j] + r * gh[2 * HD + j]);
            h[j] = (1.f - z) * n + z * h[j];
        }
        __syncthreads();
    }
    if (j < HD / 2) {
        float a = bc1[j];
        #pragma unroll 8
        for (int k = 0; k < HD; k++) a += h[k] * Wc1[k * (HD / 2) + j];
        hid[j] = fmaxf(a, 0.f);
    }
    __syncthreads();
    if (j == 0) {
        float a = bc2[0];
        for (int m = 0; m < HD / 2; m++) a += hid[m] * Wc2[m];
        out[0] = 1.f / (1.f + expf(-a));
    }
}

// ---------------- launch -----------------------------------------------------

extern "C" void kernel_launch(void* const* d_in, const int* in_sizes, int n_in,
                              void* d_out, int out_size) {
    const float* x   = (const float*)d_in[0];
    const int*   ei  = (const int*)  d_in[1];
    const int*   tgt = (const int*)  d_in[2];
    const float* W1  = (const float*)d_in[3];
    const float* b1  = (const float*)d_in[4];
    const float* W2  = (const float*)d_in[5];
    const float* b2  = (const float*)d_in[6];
    const float* Wih = (const float*)d_in[7];
    const float* Whh = (const float*)d_in[8];
    const float* bih = (const float*)d_in[9];
    const float* bhh = (const float*)d_in[10];
    const float* Wc1 = (const float*)d_in[11];
    const float* bc1 = (const float*)d_in[12];
    const float* Wc2 = (const float*)d_in[13];
    const float* bc2 = (const float*)d_in[14];
    float* out = (float*)d_out;

    const int gbN = (NN + 255) / 256;
    const int gbE = (NE + 255) / 256;
    const int gbWN = (NN * 32 + 255) / 256;   // warp-per-node kernels

    for (int t = 0; t < TS; t++) {
        const float* xt   = x   + (size_t)t * NN * FD;
        const int*   eit  = ei  + (size_t)t * 2 * NE;
        const int*   tgtt = tgt + (size_t)t * CT;

        k_init<<<gbN, 256>>>();
        k_targets<<<1, CT>>>(tgtt);
        k_prop1cnt<<<gbE, 256>>>(eit);
        k_scan<<<1, 1024>>>();
        k_prop2fill<<<gbE, 256>>>(eit);
        k_dinv<<<gbWN, 256>>>();
        k_layer1<<<592, 128>>>(xt, W1, b1, W2);
        k_zs_argmax<<<gbWN, 256>>>(b2);
        k_top<<<1, HD>>>(W2, b2, t);
    }
    k_gru<<<1, 3 * HD>>>(Wih, Whh, bih, bhh, Wc1, bc1, Wc2, bc2, out);
}

// round 4
// speedup vs baseline: 1.0277x; 1.0277x over previous
#include <cuda_runtime.h>

#define NN 20000
#define NE 400000
#define FD 64
#define CT 64
#define HD 128
#define TS 6
#define KD 67      // F + 3 label channels
#define KP 68      // padded to multiple of 4

// ---------------- scratch (static device globals; no allocation) -------------
__device__ int   g_flagA[NN];     // epoch-stamped: == ep means set
__device__ int   g_flagB[NN];
__device__ int   g_isc[NN];
__device__ int   g_cnt[NN];       // in-degree (all edges) per dst
__device__ int   g_off[NN];       // CSR row offsets
__device__ int   g_cur[NN];       // fill cursors (== row end after fill)
__device__ int   g_csrc[NE];      // CSR src indices (grouped by dst)
__device__ float g_dinv[NN];
__device__ float g_selfn[NN];
__device__ float g_h1[NN * HD];
__device__ float g_sv[NN];
__device__ float g_svd[NN];       // sv * dinv (for zs gather)
__device__ unsigned long long g_packed;
__device__ float g_seq[TS * HD];
__device__ int   g_bsum[1024];
__device__ unsigned long long g_arrive;   // barrier arrival counter
__device__ int   g_ep;                    // epoch base (monotone across replays)

// prologue: stream-ordered reset of barrier counter + epoch bump
__global__ void k_pre() { g_arrive = 0ull; g_ep += TS; g_packed = 0ull; }

__device__ __forceinline__ void gbar(unsigned long long target) {
    __syncthreads();
    if (threadIdx.x == 0) {
        __threadfence();                       // publish our writes
        atomicAdd(&g_arrive, 1ull);
        while (*((volatile unsigned long long*)&g_arrive) < target) { }
        __threadfence();                       // invalidate stale L1 before reads
    }
    __syncthreads();
}

// ---------------- the megakernel ---------------------------------------------

__global__ void __launch_bounds__(256) k_mega(
    const float* __restrict__ x, const int* __restrict__ ei,
    const int* __restrict__ tgt,
    const float* __restrict__ W1, const float* __restrict__ b1,
    const float* __restrict__ W2, const float* __restrict__ b2,
    const float* __restrict__ Wih, const float* __restrict__ Whh,
    const float* __restrict__ bih, const float* __restrict__ bhh,
    const float* __restrict__ Wc1, const float* __restrict__ bc1,
    const float* __restrict__ Wc2, const float* __restrict__ bc2,
    float* __restrict__ out)
{
    const int tid = threadIdx.x, B = blockIdx.x, G = gridDim.x;
    const int NT = G * 256;
    const int gthread = B * 256 + tid;
    const int lane = tid & 31, wid = tid >> 5;
    unsigned long long barn = 0;
    const int E0 = g_ep;                       // written by prologue, stable

    const int chunk = (NN + G - 1) / G;        // scan chunk per block
    const int nb = B * chunk;
    const int ne = (nb + chunk < NN) ? nb + chunk : NN;

    __shared__ int   s_scan[256];
    __shared__ float szrow[8][KP];
    __shared__ int   sact[8];
    __shared__ float sred[8][4];
    __shared__ int   s_pre;
    __shared__ int   s_top;
    __shared__ float s_gru[8 * HD + HD / 2];   // GRU scratch (block 0 only)

    // ---- P0: targets(0) + zero cnt ----
    {
        const int ep0 = E0 - TS + 1;
        if (B == (1 % G) && tid < CT) {
            int n = tgt[tid];
            g_flagA[n] = ep0; g_flagB[n] = ep0; g_isc[n] = ep0;
        }
        for (int i = gthread; i < NN; i += NT) g_cnt[i] = 0;
    }
    gbar(++barn * (unsigned long long)G);

    for (int t = 0; t < TS; t++) {
        const int ep = E0 - TS + 1 + t;
        const float* xt  = x  + (size_t)t * NN * FD;
        const int*   eit = ei + (size_t)t * 2 * NE;

        // ---- P1: hop 1 (A->B) + in-degree count ----
        for (int e = gthread; e < NE; e += NT) {
            int s = eit[e], d = eit[NE + e];
            atomicAdd(&g_cnt[d], 1);
            if (g_flagA[s] == ep) g_flagB[d] = ep;
            if (g_flagA[d] == ep) g_flagB[s] = ep;
        }
        gbar(++barn * G);

        // ---- P2: block-local exclusive scan of cnt chunk ----
        {
            const int CH = (chunk + 255) >> 8;
            int tb = nb + tid * CH;
            int lsum = 0;
            for (int j = 0; j < CH; j++) {
                int idx = tb + j;
                if (idx < ne) lsum += g_cnt[idx];
            }
            s_scan[tid] = lsum;
            __syncthreads();
            for (int off = 1; off < 256; off <<= 1) {
                int v = (tid >= off) ? s_scan[tid - off] : 0;
                __syncthreads();
                s_scan[tid] += v;
                __syncthreads();
            }
            int run = s_scan[tid] - lsum;          // exclusive within block
            for (int j = 0; j < CH; j++) {
                int idx = tb + j;
                if (idx < ne) { g_off[idx] = run; run += g_cnt[idx]; }
            }
            if (tid == 0) g_bsum[B] = s_scan[255];
        }
        gbar(++barn * G);

        // ---- P3: add cross-block prefix, init cursors ----
        {
            if (wid == 0) {
                int pre = 0;
                for (int j = lane; j < B; j += 32) pre += g_bsum[j];
                #pragma unroll
                for (int o = 16; o; o >>= 1) pre += __shfl_down_sync(~0u, pre, o);
                if (lane == 0) s_pre = pre;
            }
            __syncthreads();
            int pre = s_pre;
            for (int idx = nb + tid; idx < ne; idx += 256) {
                int v = g_off[idx] + pre;
                g_off[idx] = v; g_cur[idx] = v;
            }
        }
        gbar(++barn * G);

        // ---- P4: hop 2 (B->A) + CSR fill ----
        for (int e = gthread; e < NE; e += NT) {
            int s = eit[e], d = eit[NE + e];
            if (g_flagB[s] == ep) g_flagA[d] = ep;
            if (g_flagB[d] == ep) g_flagA[s] = ep;
            int p = atomicAdd(&g_cur[d], 1);
            g_csrc[p] = s;
        }
        gbar(++barn * G);

        // ---- P5: dinv/selfn (warp per node) ----
        {
            const int nwarp = NT >> 5;
            for (int i = gthread >> 5; i < NN; i += nwarp) {
                if (g_flagA[i] != ep) {
                    if (lane == 0) { g_dinv[i] = 0.f; g_selfn[i] = 0.f; }
                    continue;
                }
                int o = g_off[i], en = g_cur[i];
                int deg = 0;
                for (int e = o + lane; e < en; e += 32)
                    deg += (g_flagA[g_csrc[e]] == ep) ? 1 : 0;
                #pragma unroll
                for (int off2 = 16; off2; off2 >>= 1)
                    deg += __shfl_down_sync(~0u, deg, off2);
                if (lane == 0) {
                    float di = rsqrtf((float)deg + 1.0f);   // + self loop
                    g_dinv[i] = di; g_selfn[i] = di * di;
                }
            }
        }
        gbar(++barn * G);

        // ---- P6: layer1 gather + W1 GEMM + relu + sv ----
        {
            float rw[KP];
            const int tcol = tid & 127;
            #pragma unroll
            for (int k = 0; k < KD; k++) rw[k] = W1[k * HD + tcol];
            rw[67] = 0.f;
            float w2c = W2[tcol * HD + (HD - 1)];
            float bb  = b1[tcol];
            const int half = tid >> 7;

            for (int i0 = B * 8; i0 < NN; i0 += G * 8) {
                int i = i0 + wid;
                int active = 0;
                if (i < NN) {
                    float di = g_dinv[i];
                    if (di != 0.f) {
                        active = 1;
                        int o = g_off[i], en = g_cur[i];
                        float a0 = 0.f, a1 = 0.f, wc = 0.f, wo = 0.f;
                        for (int base = o; base < en; base += 32) {
                            int   sl = 0; float wl = 0.f; int icl = 0;
                            if (base + lane < en) {
                                sl  = g_csrc[base + lane];
                                wl  = g_dinv[sl] * di;
                                icl = (g_isc[sl] == ep) ? 1 : 0;
                            }
                            wc += icl ? wl : 0.f;
                            wo += icl ? 0.f : wl;
                            int nn2 = en - base; if (nn2 > 32) nn2 = 32;
                            #pragma unroll 4
                            for (int e2 = 0; e2 < nn2; e2++) {
                                float w = __shfl_sync(~0u, wl, e2);
                                if (w != 0.f) {
                                    int s2 = __shfl_sync(~0u, sl, e2);
                                    a0 += xt[s2 * FD + lane] * w;
                                    a1 += xt[s2 * FD + 32 + lane] * w;
                                }
                            }
                        }
                        float sn = g_selfn[i];
                        a0 += xt[i * FD + lane] * sn;
                        a1 += xt[i * FD + 32 + lane] * sn;
                        szrow[wid][lane]      = a0;
                        szrow[wid][lane + 32] = a1;
                        #pragma unroll
                        for (int off2 = 16; off2; off2 >>= 1) {
                            wc += __shfl_down_sync(~0u, wc, off2);
                            wo += __shfl_down_sync(~0u, wo, off2);
                        }
                        if (lane == 0) {
                            int ic = (g_isc[i] == ep) ? 1 : 0;
                            szrow[wid][64] = wc + (ic ? sn : 0.f);
                            szrow[wid][65] = wo + (ic ? 0.f : sn);
                            szrow[wid][66] = 0.f;
                            szrow[wid][67] = 0.f;
                        }
                    }
                }
                if (lane == 0) sact[wid] = active;
                __syncthreads();

                // GEMM: 2 subgroups of 128 threads, 4 nodes each
                float pv[4];
                #pragma unroll
                for (int r = 0; r < 4; r++) {
                    int node = half * 4 + r;
                    pv[r] = 0.f;
                    if (sact[node]) {
                        float acc = bb;
                        const float4* z4 = (const float4*)szrow[node];
                        #pragma unroll
                        for (int q = 0; q < KP / 4; q++) {
                            float4 zz = z4[q];
                            acc += zz.x * rw[4 * q]     + zz.y * rw[4 * q + 1]
                                 + zz.z * rw[4 * q + 2] + zz.w * rw[4 * q + 3];
                        }
                        float hv = fmaxf(acc, 0.f);
                        g_h1[(i0 + node) * HD + tcol] = hv;
                        pv[r] = hv * w2c;
                    }
                }
                #pragma unroll
                for (int r = 0; r < 4; r++) {
                    float p = pv[r];
                    #pragma unroll
                    for (int off2 = 16; off2; off2 >>= 1)
                        p += __shfl_down_sync(~0u, p, off2);
                    if (lane == 0) sred[wid][r] = p;
                }
                __syncthreads();
                if (tid < 8 && sact[tid] && (i0 + tid) < NN) {
                    int h2 = tid >> 2, rl = tid & 3;
                    float sv = sred[h2 * 4 + 0][rl] + sred[h2 * 4 + 1][rl]
                             + sred[h2 * 4 + 2][rl] + sred[h2 * 4 + 3][rl];
                    g_sv[i0 + tid]  = sv;
                    g_svd[i0 + tid] = sv * g_dinv[i0 + tid];
                }
                __syncthreads();
            }
        }
        gbar(++barn * G);

        // ---- P7: scalar layer-2 gather + argmax ----
        {
            const int nwarp = NT >> 5;
            for (int i = gthread >> 5; i < NN; i += nwarp) {
                if (g_flagA[i] != ep) continue;
                int o = g_off[i], en = g_cur[i];
                float acc = 0.f;
                for (int e = o + lane; e < en; e += 32)
                    acc += g_svd[g_csrc[e]];
                #pragma unroll
                for (int off2 = 16; off2; off2 >>= 1)
                    acc += __shfl_down_sync(~0u, acc, off2);
                if (lane == 0) {
                    float v = acc * g_dinv[i] + g_sv[i] * g_selfn[i] + b2[HD - 1];
                    v = fmaxf(v, 0.f);   // >=0: float bits monotone as unsigned
                    unsigned long long key =
                        ((unsigned long long)__float_as_uint(v) << 32) |
                        (unsigned long long)(0xFFFFFFFFu - (unsigned)i);
                    atomicMax(&g_packed, key);
                }
            }
        }
        gbar(++barn * G);

        // ---- P8: top (block 0) || targets(t+1) || zero cnt (all) ----
        {
            if (B == 0) {
                if (tid == 0)
                    s_top = (int)(0xFFFFFFFFu - (unsigned)(g_packed & 0xFFFFFFFFull));
                __syncthreads();
                int top = s_top;
                if (tid < HD) {
                    float di = g_dinv[top];
                    int o = g_off[top], en = g_cur[top];
                    float acc = g_h1[top * HD + tid] * g_selfn[top];
                    for (int e = o; e < en; e++) {
                        int s2 = g_csrc[e];
                        float w = g_dinv[s2] * di;
                        if (w != 0.f) acc += g_h1[s2 * HD + tid] * w;
                    }
                    ((float*)szrow)[tid] = acc;
                }
                __syncthreads();
                if (tid < HD) {
                    const float* zf = (const float*)szrow;
                    float a = b2[tid];
                    #pragma unroll 8
                    for (int k = 0; k < HD; k++) a += zf[k] * W2[k * HD + tid];
                    g_seq[t * HD + tid] = fmaxf(a, 0.f);
                }
                __syncthreads();
                if (tid == 0) g_packed = 0ull;
            }
            if (t + 1 < TS && B == (1 % G) && tid < CT) {
                int n = tgt[(t + 1) * CT + tid];
                int ep1 = ep + 1;
                g_flagA[n] = ep1; g_flagB[n] = ep1; g_isc[n] = ep1;
            }
            for (int i = gthread; i < NN; i += NT) g_cnt[i] = 0;
        }
        gbar(++barn * G);
    }

    // ---- GRU + classifier head: block 0 only ----
    if (B == 0) {
        float* h   = s_gru;
        float* xv  = s_gru + HD;
        float* gi  = s_gru + 2 * HD;
        float* gh  = s_gru + 5 * HD;
        float* hid = s_gru + 8 * HD;
        for (int j = tid; j < HD; j += 256) h[j] = 0.f;
        __syncthreads();
        for (int t = 0; t < TS; t++) {
            for (int j = tid; j < HD; j += 256) xv[j] = g_seq[t * HD + j];
            __syncthreads();
            for (int j = tid; j < 3 * HD; j += 256) {
                float a = bih[j], bs = bhh[j];
                #pragma unroll 8
                for (int k = 0; k < HD; k++) {
                    a  += Wih[j * HD + k] * xv[k];
                    bs += Whh[j * HD + k] * h[k];
                }
                gi[j] = a; gh[j] = bs;
            }
            __syncthreads();
            for (int j = tid; j < HD; j += 256) {
                float r  = 1.f / (1.f + expf(-(gi[j] + gh[j])));
                float z  = 1.f / (1.f + expf(-(gi[HD + j] + gh[HD + j])));
                float n2 = tanhf(gi[2 * HD + j] + r * gh[2 * HD + j]);
                h[j] = (1.f - z) * n2 + z * h[j];
            }
            __syncthreads();
        }
        for (int j = tid; j < HD / 2; j += 256) {
            float a = bc1[j];
            #pragma unroll 8
            for (int k = 0; k < HD; k++) a += h[k] * Wc1[k * (HD / 2) + j];
            hid[j] = fmaxf(a, 0.f);
        }
        __syncthreads();
        if (tid == 0) {
            float a = bc2[0];
            for (int m = 0; m < HD / 2; m++) a += hid[m] * Wc2[m];
            out[0] = 1.f / (1.f + expf(-a));
        }
    }
}

// ---------------- launch -----------------------------------------------------

extern "C" void kernel_launch(void* const* d_in, const int* in_sizes, int n_in,
                              void* d_out, int out_size) {
    const float* x   = (const float*)d_in[0];
    const int*   ei  = (const int*)  d_in[1];
    const int*   tgt = (const int*)  d_in[2];
    const float* W1  = (const float*)d_in[3];
    const float* b1  = (const float*)d_in[4];
    const float* W2  = (const float*)d_in[5];
    const float* b2  = (const float*)d_in[6];
    const float* Wih = (const float*)d_in[7];
    const float* Whh = (const float*)d_in[8];
    const float* bih = (const float*)d_in[9];
    const float* bhh = (const float*)d_in[10];
    const float* Wc1 = (const float*)d_in[11];
    const float* bc1 = (const float*)d_in[12];
    const float* Wc2 = (const float*)d_in[13];
    const float* bc2 = (const float*)d_in[14];
    float* out = (float*)d_out;

    int dev = 0;
    cudaGetDevice(&dev);
    int nsm = 0;
    cudaDeviceGetAttribute(&nsm, cudaDevAttrMultiProcessorCount, dev);
    int perSM = 0;
    cudaOccupancyMaxActiveBlocksPerMultiprocessor(&perSM, k_mega, 256, 0);
    if (perSM < 1) perSM = 1;
    int G = nsm * perSM;
    if (G < 1) G = 1;
    if (G > 1024) G = 1024;

    k_pre<<<1, 1>>>();
    k_mega<<<G, 256>>>(x, ei, tgt, W1, b1, W2, b2,
                       Wih, Whh, bih, bhh, Wc1, bc1, Wc2, bc2, out);
}

// round 5
// speedup vs baseline: 1.3768x; 1.3397x over previous
#include <cuda_runtime.h>

#define NN 20000
#define NE 400000
#define FD 64
#define CT 64
#define HD 128
#define TS 6
#define KD 67      // F + 3 label channels
#define KP 68      // padded to multiple of 4
#define NG 6       // concurrent snapshot groups

// ---------------- scratch (static device globals; no allocation) -------------
__device__ int   g_flagA[NG][NN];
__device__ int   g_flagB[NG][NN];
__device__ int   g_isc[NG][2][NN];    // ping-pong by snapshot parity
__device__ int   g_cnt[NG][NN];
__device__ int   g_off[NG][NN];
__device__ int   g_cur[NG][NN];       // == row end after fill
__device__ int   g_csrc[NG][NE];
__device__ float g_dinv[NG][NN];
__device__ float g_selfn[NG][NN];
__device__ float g_sv[NG][NN];
__device__ float g_svd[NG][NN];       // sv * dinv (0 for out-of-sub)
__device__ unsigned long long g_packed[NG];
__device__ float g_seq[TS * HD];
__device__ float g_gi[TS][3 * HD];    // precomputed Wih @ seq[t] + bih
__device__ int   g_bsum[NG][256];
__device__ unsigned long long g_bar[NG * 16];   // one 128B line per group
__device__ unsigned long long g_done;

__global__ void k_pre() {
    int i = threadIdx.x;
    if (i < NG * 16) g_bar[i] = 0ull;
    if (i == 0) g_done = 0ull;
}

// group-local grid barrier (gpb blocks per group)
__device__ __forceinline__ void gbar(int grp, unsigned long long target) {
    __syncthreads();
    if (threadIdx.x == 0) {
        __threadfence();
        atomicAdd(&g_bar[grp * 16], 1ull);
        while (*((volatile unsigned long long*)&g_bar[grp * 16]) < target)
            __nanosleep(64);
        __threadfence();
    }
    __syncthreads();
}

// warp-collective: build one node's 68-float normalized feature row
__device__ __forceinline__ void gather_row(const float* __restrict__ xt,
                                           int grp, int par, int v,
                                           float* dst, int lane) {
    float di = g_dinv[grp][v];
    int o = g_off[grp][v], en = g_cur[grp][v];
    float a0 = 0.f, a1 = 0.f, wc = 0.f, wo = 0.f;
    for (int base = o; base < en; base += 32) {
        int sl = 0; float wl = 0.f; int icl = 0;
        if (base + lane < en) {
            sl  = g_csrc[grp][base + lane];
            wl  = g_dinv[grp][sl] * di;
            icl = g_isc[grp][par][sl];
        }
        wc += icl ? wl : 0.f;
        wo += icl ? 0.f : wl;
        int nn2 = en - base; if (nn2 > 32) nn2 = 32;
        #pragma unroll 4
        for (int e2 = 0; e2 < nn2; e2++) {
            float w = __shfl_sync(~0u, wl, e2);
            if (w != 0.f) {
                int s2 = __shfl_sync(~0u, sl, e2);
                a0 += xt[s2 * FD + lane] * w;
                a1 += xt[s2 * FD + 32 + lane] * w;
            }
        }
    }
    float sn = g_selfn[grp][v];
    a0 += xt[v * FD + lane] * sn;
    a1 += xt[v * FD + 32 + lane] * sn;
    dst[lane]      = a0;
    dst[lane + 32] = a1;
    #pragma unroll
    for (int off2 = 16; off2; off2 >>= 1) {
        wc += __shfl_down_sync(~0u, wc, off2);
        wo += __shfl_down_sync(~0u, wo, off2);
    }
    if (lane == 0) {
        int ic = g_isc[grp][par][v];
        dst[64] = wc + (ic ? sn : 0.f);
        dst[65] = wo + (ic ? 0.f : sn);
        dst[66] = 0.f;
        dst[67] = 0.f;
    }
}

// membership init for snapshot t of group grp: flags/isc/cnt (+ packed reset)
__device__ __forceinline__ void init_snapshot(const int* __restrict__ tgt,
                                              int grp, int t, int gb, int gpb,
                                              int tid, int* s_tgt) {
    for (int j = tid; j < CT; j += 256) s_tgt[j] = tgt[t * CT + j];
    __syncthreads();
    int par = t & 1;
    for (int i = gb * 256 + tid; i < NN; i += gpb * 256) {
        int m = 0;
        #pragma unroll 8
        for (int j = 0; j < CT; j++) m |= (s_tgt[j] == i);
        g_flagA[grp][i] = m;
        g_flagB[grp][i] = m;
        g_isc[grp][par][i] = m;
        g_cnt[grp][i] = 0;
    }
    if (gb == 0 && tid == 0) g_packed[grp] = 0ull;
}

// ---------------- the megakernel ---------------------------------------------

__global__ void __launch_bounds__(256) k_mega(
    const float* __restrict__ x, const int* __restrict__ ei,
    const int* __restrict__ tgt,
    const float* __restrict__ W1, const float* __restrict__ b1,
    const float* __restrict__ W2, const float* __restrict__ b2,
    const float* __restrict__ Wih, const float* __restrict__ Whh,
    const float* __restrict__ bih, const float* __restrict__ bhh,
    const float* __restrict__ Wc1, const float* __restrict__ bc1,
    const float* __restrict__ Wc2, const float* __restrict__ bc2,
    float* __restrict__ out)
{
    const int tid = threadIdx.x, B = blockIdx.x, G = gridDim.x;
    const int gpb = G / NG;
    const int lane = tid & 31, wid = tid >> 5;
    const int tcol = tid & 127, half = tid >> 7;

    __shared__ int   s_scan[256];
    __shared__ float szrow[8][KP];
    __shared__ int   sact[8];
    __shared__ float sred[8][4];
    __shared__ int   s_tgt[CT];
    __shared__ int   s_pre, s_top, s_m;
    __shared__ int   s_list[512];
    __shared__ float s_wl[512];
    __shared__ float s_z2[HD];
    __shared__ float s_sq[HD];
    __shared__ float s_h[HD];
    __shared__ float s_gh[3 * HD];
    __shared__ float s_hid[HD / 2];

    if (B < NG * gpb) {
        const int grp = B / gpb;
        const int gb  = B % gpb;
        unsigned long long barn = 0;

        // W1 column tcol in registers (used in P6 GEMM and P8 recompute)
        float rw[KP];
        #pragma unroll
        for (int k = 0; k < KD; k++) rw[k] = W1[k * HD + tcol];
        rw[67] = 0.f;
        const float w2c = W2[tcol * HD + (HD - 1)];
        const float bb  = b1[tcol];

        const int t0 = grp;                   // group grp owns snapshot grp
        const float* xt  = x  + (size_t)t0 * NN * FD;
        const int*   eit = ei + (size_t)t0 * 2 * NE;
        const int par = t0 & 1;

        const int chunk = (NN + gpb - 1) / gpb;
        const int nb = gb * chunk;
        const int nen = (nb + chunk < NN) ? nb + chunk : NN;

        // ---- P0: membership init ----
        init_snapshot(tgt, grp, t0, gb, gpb, tid, s_tgt);
        gbar(grp, ++barn * (unsigned long long)gpb);

        // ---- P1: hop 1 (A->B) + in-degree count ----
        for (int e = gb * 256 + tid; e < NE; e += gpb * 256) {
            int s = eit[e], d = eit[NE + e];
            atomicAdd(&g_cnt[grp][d], 1);
            if (g_flagA[grp][s]) g_flagB[grp][d] = 1;
            if (g_flagA[grp][d]) g_flagB[grp][s] = 1;
        }
        gbar(grp, ++barn * gpb);

        // ---- P2: block-local exclusive scan of cnt chunk ----
        {
            const int CH = (chunk + 255) >> 8;
            int tb = nb + tid * CH;
            int lsum = 0;
            for (int j = 0; j < CH; j++)
                if (tb + j < nen) lsum += g_cnt[grp][tb + j];
            s_scan[tid] = lsum;
            __syncthreads();
            for (int off = 1; off < 256; off <<= 1) {
                int v = (tid >= off) ? s_scan[tid - off] : 0;
                __syncthreads();
                s_scan[tid] += v;
                __syncthreads();
            }
            int run = s_scan[tid] - lsum;
            for (int j = 0; j < CH; j++) {
                int idx = tb + j;
                if (idx < nen) { g_off[grp][idx] = run; run += g_cnt[grp][idx]; }
            }
            if (tid == 0) g_bsum[grp][gb] = s_scan[255];
        }
        gbar(grp, ++barn * gpb);

        // ---- P3: cross-block prefix, init cursors ----
        {
            if (wid == 0) {
                int pre = 0;
                for (int j = lane; j < gb; j += 32) pre += g_bsum[grp][j];
                #pragma unroll
                for (int o = 16; o; o >>= 1) pre += __shfl_down_sync(~0u, pre, o);
                if (lane == 0) s_pre = pre;
            }
            __syncthreads();
            int pre = s_pre;
            for (int idx = nb + tid; idx < nen; idx += 256) {
                int v = g_off[grp][idx] + pre;
                g_off[grp][idx] = v; g_cur[grp][idx] = v;
            }
        }
        gbar(grp, ++barn * gpb);

        // ---- P4: hop 2 (B->A) + CSR fill ----
        for (int e = gb * 256 + tid; e < NE; e += gpb * 256) {
            int s = eit[e], d = eit[NE + e];
            if (g_flagB[grp][s]) g_flagA[grp][d] = 1;
            if (g_flagB[grp][d]) g_flagA[grp][s] = 1;
            int p = atomicAdd(&g_cur[grp][d], 1);
            g_csrc[grp][p] = s;
        }
        gbar(grp, ++barn * gpb);

        // ---- P5: dinv/selfn ----
        for (int i = gb * 8 + wid; i < NN; i += gpb * 8) {
            if (!g_flagA[grp][i]) {
                if (lane == 0) { g_dinv[grp][i] = 0.f; g_selfn[grp][i] = 0.f; }
                continue;
            }
            int o = g_off[grp][i], en = g_cur[grp][i];
            int deg = 0;
            for (int e = o + lane; e < en; e += 32)
                deg += g_flagA[grp][g_csrc[grp][e]];
            #pragma unroll
            for (int o2 = 16; o2; o2 >>= 1)
                deg += __shfl_down_sync(~0u, deg, o2);
            if (lane == 0) {
                float di = rsqrtf((float)deg + 1.0f);
                g_dinv[grp][i] = di; g_selfn[grp][i] = di * di;
            }
        }
        gbar(grp, ++barn * gpb);

        // ---- P6: layer1 gather + W1 GEMM + sv (no h1 store) ----
        for (int i0 = gb * 8; i0 < NN; i0 += gpb * 8) {
            int i = i0 + wid;
            int active = 0;
            if (i < NN && g_dinv[grp][i] != 0.f) {
                active = 1;
                gather_row(xt, grp, par, i, szrow[wid], lane);
            }
            if (lane == 0) sact[wid] = active;
            __syncthreads();

            float pv[4];
            #pragma unroll
            for (int r = 0; r < 4; r++) {
                int node = half * 4 + r;
                pv[r] = 0.f;
                if (sact[node]) {
                    float acc = bb;
                    const float4* z4 = (const float4*)szrow[node];
                    #pragma unroll
                    for (int q = 0; q < KP / 4; q++) {
                        float4 zz = z4[q];
                        acc += zz.x * rw[4 * q]     + zz.y * rw[4 * q + 1]
                             + zz.z * rw[4 * q + 2] + zz.w * rw[4 * q + 3];
                    }
                    pv[r] = fmaxf(acc, 0.f) * w2c;
                }
            }
            #pragma unroll
            for (int r = 0; r < 4; r++) {
                float p = pv[r];
                #pragma unroll
                for (int o2 = 16; o2; o2 >>= 1)
                    p += __shfl_down_sync(~0u, p, o2);
                if (lane == 0) sred[wid][r] = p;
            }
            __syncthreads();
            if (tid < 8 && (i0 + tid) < NN) {
                if (sact[tid]) {
                    int h2 = tid >> 2, rl = tid & 3;
                    float sv = sred[h2 * 4 + 0][rl] + sred[h2 * 4 + 1][rl]
                             + sred[h2 * 4 + 2][rl] + sred[h2 * 4 + 3][rl];
                    g_sv[grp][i0 + tid]  = sv;
                    g_svd[grp][i0 + tid] = sv * g_dinv[grp][i0 + tid];
                } else {
                    g_svd[grp][i0 + tid] = 0.f;   // kill stale values
                }
            }
            __syncthreads();
        }
        gbar(grp, ++barn * gpb);

        // ---- P7: scalar layer-2 gather + argmax ----
        {
            const float b2h = b2[HD - 1];
            for (int i = gb * 8 + wid; i < NN; i += gpb * 8) {
                if (!g_flagA[grp][i]) continue;
                int o = g_off[grp][i], en = g_cur[grp][i];
                float acc = 0.f;
                for (int e = o + lane; e < en; e += 32)
                    acc += g_svd[grp][g_csrc[grp][e]];
                #pragma unroll
                for (int o2 = 16; o2; o2 >>= 1)
                    acc += __shfl_down_sync(~0u, acc, o2);
                if (lane == 0) {
                    float v = acc * g_dinv[grp][i]
                            + g_sv[grp][i] * g_selfn[grp][i] + b2h;
                    v = fmaxf(v, 0.f);   // >=0: bits monotone as unsigned
                    unsigned long long key =
                        ((unsigned long long)__float_as_uint(v) << 32) |
                        (unsigned long long)(0xFFFFFFFFu - (unsigned)i);
                    atomicMax(&g_packed[grp], key);
                }
            }
        }
        gbar(grp, ++barn * gpb);

        // ---- P8 (gb 0): top-node layer2 recompute + seq + gi precompute ----
        if (gb == 0) {
            if (tid == 0) {
                s_top = (int)(0xFFFFFFFFu -
                              (unsigned)(g_packed[grp] & 0xFFFFFFFFull));
                s_m = 0;
            }
            __syncthreads();
            int top = s_top;
            float dtop = g_dinv[grp][top];
            int o = g_off[grp][top], en = g_cur[grp][top];
            for (int e = o + tid; e < en; e += 256) {
                int s = g_csrc[grp][e];
                float w = g_dinv[grp][s] * dtop;
                if (w != 0.f) {
                    int p = atomicAdd(&s_m, 1);
                    if (p < 511) { s_list[p] = s; s_wl[p] = w; }
                }
            }
            __syncthreads();
            if (tid == 0) {
                int p = s_m; if (p > 511) p = 511;
                s_list[p] = top; s_wl[p] = g_selfn[grp][top];
                s_m = p + 1;
            }
            __syncthreads();
            int m = s_m;
            float z2acc = 0.f;
            for (int b0 = 0; b0 < m; b0 += 8) {
                int r = b0 + wid;
                if (r < m) gather_row(xt, grp, par, s_list[r], szrow[wid], lane);
                __syncthreads();
                #pragma unroll
                for (int rr = 0; rr < 4; rr++) {
                    int node = half * 4 + rr;
                    int gidx = b0 + node;
                    if (gidx < m) {
                        float acc = bb;
                        const float4* z4 = (const float4*)szrow[node];
                        #pragma unroll
                        for (int q = 0; q < KP / 4; q++) {
                            float4 zz = z4[q];
                            acc += zz.x * rw[4 * q]     + zz.y * rw[4 * q + 1]
                                 + zz.z * rw[4 * q + 2] + zz.w * rw[4 * q + 3];
                        }
                        z2acc += fmaxf(acc, 0.f) * s_wl[gidx];
                    }
                }
                __syncthreads();
            }
            if (half == 1) s_z2[tcol] = z2acc;
            __syncthreads();
            if (half == 0) s_z2[tcol] = z2acc + s_z2[tcol];
            __syncthreads();
            if (tid < HD) {
                float a = b2[tid];
                #pragma unroll 8
                for (int k = 0; k < HD; k++) a += s_z2[k] * W2[k * HD + tid];
                float sq = fmaxf(a, 0.f);
                g_seq[t0 * HD + tid] = sq;
                s_sq[tid] = sq;
            }
            __syncthreads();
            // gi[t0] = Wih @ seq + bih  (warp per row, coalesced)
            for (int j = wid; j < 3 * HD; j += 8) {
                float dotv = 0.f;
                for (int k = lane; k < HD; k += 32)
                    dotv += Wih[j * HD + k] * s_sq[k];
                #pragma unroll
                for (int o2 = 16; o2; o2 >>= 1)
                    dotv += __shfl_down_sync(~0u, dotv, o2);
                if (lane == 0) g_gi[t0][j] = dotv + bih[j];
            }
        }
    }

    // ---- final: all blocks arrive; block 0 runs GRU + head ----
    if (B != 0) {
        __syncthreads();
        if (tid == 0) { __threadfence(); atomicAdd(&g_done, 1ull); }
        return;
    }
    if (tid == 0) {
        while (*((volatile unsigned long long*)&g_done) <
               (unsigned long long)(G - 1))
            __nanosleep(128);
        __threadfence();
    }
    __syncthreads();

    if (tid < HD) s_h[tid] = 0.f;
    __syncthreads();
    for (int t = 0; t < TS; t++) {
        // gh = Whh @ h + bhh (warp per row, coalesced)
        for (int j = wid; j < 3 * HD; j += 8) {
            float dotv = 0.f;
            for (int k = lane; k < HD; k += 32)
                dotv += Whh[j * HD + k] * s_h[k];
            #pragma unroll
            for (int o2 = 16; o2; o2 >>= 1)
                dotv += __shfl_down_sync(~0u, dotv, o2);
            if (lane == 0) s_gh[j] = dotv + bhh[j];
        }
        __syncthreads();
        if (tid < HD) {
            float r  = 1.f / (1.f + expf(-(g_gi[t][tid] + s_gh[tid])));
            float z  = 1.f / (1.f + expf(-(g_gi[t][HD + tid] + s_gh[HD + tid])));
            float n2 = tanhf(g_gi[t][2 * HD + tid] + r * s_gh[2 * HD + tid]);
            s_h[tid] = (1.f - z) * n2 + z * s_h[tid];
        }
        __syncthreads();
    }
    if (tid < HD / 2) {
        float a = bc1[tid];
        #pragma unroll 8
        for (int k = 0; k < HD; k++) a += s_h[k] * Wc1[k * (HD / 2) + tid];
        s_hid[tid] = fmaxf(a, 0.f);
    }
    __syncthreads();
    if (tid == 0) {
        float a = bc2[0];
        for (int m2 = 0; m2 < HD / 2; m2++) a += s_hid[m2] * Wc2[m2];
        out[0] = 1.f / (1.f + expf(-a));
    }
}

// ---------------- launch -----------------------------------------------------

extern "C" void kernel_launch(void* const* d_in, const int* in_sizes, int n_in,
                              void* d_out, int out_size) {
    const float* x   = (const float*)d_in[0];
    const int*   ei  = (const int*)  d_in[1];
    const int*   tgt = (const int*)  d_in[2];
    const float* W1  = (const float*)d_in[3];
    const float* b1  = (const float*)d_in[4];
    const float* W2  = (const float*)d_in[5];
    const float* b2  = (const float*)d_in[6];
    const float* Wih = (const float*)d_in[7];
    const float* Whh = (const float*)d_in[8];
    const float* bih = (const float*)d_in[9];
    const float* bhh = (const float*)d_in[10];
    const float* Wc1 = (const float*)d_in[11];
    const float* bc1 = (const float*)d_in[12];
    const float* Wc2 = (const float*)d_in[13];
    const float* bc2 = (const float*)d_in[14];
    float* out = (float*)d_out;

    int dev = 0;
    cudaGetDevice(&dev);
    int nsm = 0;
    cudaDeviceGetAttribute(&nsm, cudaDevAttrMultiProcessorCount, dev);
    int perSM = 0;
    cudaOccupancyMaxActiveBlocksPerMultiprocessor(&perSM, k_mega, 256, 0);
    if (perSM < 1) perSM = 1;
    int G = nsm * perSM;
    if (G < NG) G = NG;
    if (G > NG * 256) G = NG * 256;

    k_pre<<<1, 128>>>();
    k_mega<<<G, 256>>>(x, ei, tgt, W1, b1, W2, b2,
                       Wih, Whh, bih, bhh, Wc1, bc1, Wc2, bc2, out);
}